// round 8
// baseline (speedup 1.0000x reference)
#include <cuda_runtime.h>
#include <cstdint>

#define M_DIM 256
#define I_DIM 512
#define D_DIM 128
#define H_DIM 128
#define NPROD 256              // producer blocks (2 rows each)
#define NCONS 768              // consumer blocks
#define NBLK  (NPROD + NCONS)  // 1024 total, all co-resident (7/SM * 148 = 1036)

// Scratch (device globals; zero-initialized; no allocation allowed)
__device__ float g_L[I_DIM * D_DIM];
__device__ float g_R[I_DIM * D_DIM];
__device__ int   g_ready0;    // producers done with rows [0,256)
__device__ int   g_ready1;    // producers done with rows [256,512)
__device__ int   g_consumed;  // consumer arrival; last one resets counters

__global__ void __launch_bounds__(256, 7) fused_kernel(
    const float* __restrict__ x,
    const float* __restrict__ ln_g, const float* __restrict__ ln_b,
    const float* __restrict__ wl, const float* __restrict__ bl,
    const float* __restrict__ wr, const float* __restrict__ br,
    const float* __restrict__ wo, const float* __restrict__ bo,
    float* __restrict__ out)
{
    const int tid = threadIdx.x;

    if (blockIdx.x < NPROD) {
        // =================== PRODUCER: LN + proj for 2 rows ===================
        const int warp = tid >> 5;
        const int lane = tid & 31;
        const float4* __restrict__ x4 = reinterpret_cast<const float4*>(x);

        __shared__ float part[8][D_DIM];
        __shared__ float xs[D_DIM];
        __shared__ float ls[H_DIM], rs[H_DIM];

        #pragma unroll 1
        for (int r = 0; r < 2; r++) {
            const int i = blockIdx.x + r * NPROD;

            float a0 = 0.f, a1 = 0.f, a2 = 0.f, a3 = 0.f;
            #pragma unroll 1
            for (int t = 0; t < 32; t += 4) {
                float4 v[4];
                #pragma unroll
                for (int u = 0; u < 4; u++) {
                    const int m = warp + (t + u) * 8;
                    v[u] = x4[((size_t)m * I_DIM + i) * 32 + lane];
                }
                float s[4], sq[4];
                #pragma unroll
                for (int u = 0; u < 4; u++) {
                    s[u]  = v[u].x + v[u].y + v[u].z + v[u].w;
                    sq[u] = v[u].x*v[u].x + v[u].y*v[u].y
                          + v[u].z*v[u].z + v[u].w*v[u].w;
                }
                #pragma unroll
                for (int o = 16; o; o >>= 1) {
                    #pragma unroll
                    for (int u = 0; u < 4; u++) {
                        s[u]  += __shfl_xor_sync(0xffffffffu, s[u],  o);
                        sq[u] += __shfl_xor_sync(0xffffffffu, sq[u], o);
                    }
                }
                #pragma unroll
                for (int u = 0; u < 4; u++) {
                    const float mu   = s[u] * (1.f / 128.f);
                    const float var  = sq[u] * (1.f / 128.f) - mu * mu;
                    const float rstd = rsqrtf(var + 1e-5f);
                    a0 += (v[u].x - mu) * rstd;
                    a1 += (v[u].y - mu) * rstd;
                    a2 += (v[u].z - mu) * rstd;
                    a3 += (v[u].w - mu) * rstd;
                }
            }

            part[warp][lane * 4 + 0] = a0;
            part[warp][lane * 4 + 1] = a1;
            part[warp][lane * 4 + 2] = a2;
            part[warp][lane * 4 + 3] = a3;
            __syncthreads();

            if (tid < D_DIM) {
                float sum = 0.f;
                #pragma unroll
                for (int w = 0; w < 8; w++) sum += part[w][tid];
                xs[tid] = sum * (1.f / (float)M_DIM) * ln_g[tid] + ln_b[tid];
            }
            __syncthreads();

            const int h    = tid & 127;
            const int side = tid >> 7;
            {   // stage 1
                const float* __restrict__ w1 = side ? wr : wl;
                float acc = side ? br[h] : bl[h];
                #pragma unroll 8
                for (int c = 0; c < D_DIM; c++)
                    acc += xs[c] * w1[c * H_DIM + h];
                if (side) rs[h] = acc; else ls[h] = acc;
            }
            __syncthreads();
            {   // stage 2
                const float* __restrict__ v = side ? rs : ls;
                float acc = side ? bo[h] : 0.f;
                #pragma unroll 8
                for (int c = 0; c < H_DIM; c++)
                    acc += v[c] * wo[c * D_DIM + h];
                if (side) g_R[i * D_DIM + h] = acc;
                else      g_L[i * D_DIM + h] = acc;
            }

            __threadfence();       // each thread: its L/R stores visible
            __syncthreads();       // all threads fenced
            if (tid == 0) {
                if (r == 0) atomicAdd(&g_ready0, 1);
                else        atomicAdd(&g_ready1, 1);
            }
            __syncthreads();       // protect smem reuse in next r
        }
    } else {
        // =================== CONSUMER: out[i,j,:] = L[i]+R[j] =================
        const int c  = blockIdx.x - NPROD;
        const int d4 = tid & 31;
        const int jl = tid >> 5;
        const float4* __restrict__ L4 = reinterpret_cast<const float4*>(g_L);
        const float4* __restrict__ R4 = reinterpret_cast<const float4*>(g_R);
        float4* __restrict__ o4 = reinterpret_cast<float4*>(out);

        // ---- wait for batch 0 (rows [0,256)) ----
        if (tid == 0) {
            while (*(volatile int*)&g_ready0 < NPROD) __nanosleep(256);
        }
        __syncthreads();

        // quadrant (i<256, j<256): 256*8 = 2048 units of (i, 32 j's)
        #pragma unroll 1
        for (int u = c; u < 2048; u += NCONS) {
            const int i  = u >> 3;
            const int j0 = (u & 7) * 32;
            const float4 Lv = L4[i * 32 + d4];
            #pragma unroll
            for (int p = 0; p < 4; p++) {
                const int j = j0 + jl + p * 8;
                const float4 Rv = __ldg(&R4[j * 32 + d4]);
                float4 o;
                o.x = Lv.x + Rv.x; o.y = Lv.y + Rv.y;
                o.z = Lv.z + Rv.z; o.w = Lv.w + Rv.w;
                __stcs(&o4[((size_t)i * I_DIM + j) * 32 + d4], o);
            }
        }

        // ---- wait for batch 1 (rows [256,512)) ----
        if (tid == 0) {
            while (*(volatile int*)&g_ready1 < NPROD) __nanosleep(256);
        }
        __syncthreads();

        // remaining 3 quadrants: 3 * 2048 = 6144 units
        #pragma unroll 1
        for (int u = c; u < 6144; u += NCONS) {
            const int q  = u >> 11;         // 0..2
            const int r2 = u & 2047;
            int i, j0;
            if (q == 0)      { i = r2 >> 3;         j0 = 256 + (r2 & 7) * 32; }
            else if (q == 1) { i = 256 + (r2 >> 3); j0 = (r2 & 7) * 32; }
            else             { i = 256 + (r2 >> 3); j0 = 256 + (r2 & 7) * 32; }

            const float4 Lv = L4[i * 32 + d4];
            #pragma unroll
            for (int p = 0; p < 4; p++) {
                const int j = j0 + jl + p * 8;
                const float4 Rv = __ldg(&R4[j * 32 + d4]);
                float4 o;
                o.x = Lv.x + Rv.x; o.y = Lv.y + Rv.y;
                o.z = Lv.z + Rv.z; o.w = Lv.w + Rv.w;
                __stcs(&o4[((size_t)i * I_DIM + j) * 32 + d4], o);
            }
        }

        // ---- arrival; last consumer resets counters for next graph replay ----
        __syncthreads();
        if (tid == 0) {
            const int old = atomicAdd(&g_consumed, 1);
            if (old == NCONS - 1) {
                g_ready0 = 0;
                g_ready1 = 0;
                g_consumed = 0;
                __threadfence();
            }
        }
    }
}

// ---------------------------------------------------------------------------
extern "C" void kernel_launch(void* const* d_in, const int* in_sizes, int n_in,
                              void* d_out, int out_size)
{
    const float* x    = (const float*)d_in[0];
    const float* ln_g = (const float*)d_in[1];
    const float* ln_b = (const float*)d_in[2];
    const float* wl   = (const float*)d_in[3];
    const float* bl   = (const float*)d_in[4];
    const float* wr   = (const float*)d_in[5];
    const float* br   = (const float*)d_in[6];
    const float* wo   = (const float*)d_in[7];
    const float* bo   = (const float*)d_in[8];
    float* out = (float*)d_out;

    fused_kernel<<<NBLK, 256>>>(x, ln_g, ln_b, wl, bl, wr, br, wo, bo, out);
}

// round 10
// speedup vs baseline: 1.1586x; 1.1586x over previous
#include <cuda_runtime.h>
#include <cstdint>

#define M_DIM 256
#define I_DIM 512
#define D_DIM 128
#define H_DIM 128
#define NBLK  1024           // (512 rows) x (2 m-halves); all co-resident

// Scratch (device globals; zero-initialized; no allocation allowed)
__device__ float g_part[2 * I_DIM * D_DIM];
__device__ float g_L[I_DIM * D_DIM];
__device__ float g_R[I_DIM * D_DIM];
__device__ int   g_cntA[I_DIM];   // per-row arrivals (2); winner resets
__device__ int   g_readyRows;     // rows fully projected
__device__ int   g_done;          // broadcast arrivals; last resets globals

__global__ void __launch_bounds__(256, 7) fused_kernel(
    const float* __restrict__ x,
    const float* __restrict__ ln_g, const float* __restrict__ ln_b,
    const float* __restrict__ wl, const float* __restrict__ bl,
    const float* __restrict__ wr, const float* __restrict__ br,
    const float* __restrict__ wo, const float* __restrict__ bo,
    float* __restrict__ out)
{
    const int tid  = threadIdx.x;
    const int i    = blockIdx.x >> 1;   // row
    const int z    = blockIdx.x & 1;    // m-half
    const int warp = tid >> 5;
    const int lane = tid & 31;

    // ================= Phase A: LN partial over 128 m's =================
    {
        const float4* __restrict__ x4 = reinterpret_cast<const float4*>(x);
        float a0 = 0.f, a1 = 0.f, a2 = 0.f, a3 = 0.f;
        const int m_base = z * 128 + warp;

        #pragma unroll 1
        for (int t = 0; t < 16; t += 4) {
            float4 v[4];
            #pragma unroll
            for (int u = 0; u < 4; u++) {
                const int m = m_base + (t + u) * 8;
                v[u] = x4[((size_t)m * I_DIM + i) * 32 + lane];
            }
            float s[4], sq[4];
            #pragma unroll
            for (int u = 0; u < 4; u++) {
                s[u]  = v[u].x + v[u].y + v[u].z + v[u].w;
                sq[u] = v[u].x*v[u].x + v[u].y*v[u].y
                      + v[u].z*v[u].z + v[u].w*v[u].w;
            }
            #pragma unroll
            for (int o = 16; o; o >>= 1) {
                #pragma unroll
                for (int u = 0; u < 4; u++) {
                    s[u]  += __shfl_xor_sync(0xffffffffu, s[u],  o);
                    sq[u] += __shfl_xor_sync(0xffffffffu, sq[u], o);
                }
            }
            #pragma unroll
            for (int u = 0; u < 4; u++) {
                const float mu   = s[u] * (1.f / 128.f);
                const float var  = sq[u] * (1.f / 128.f) - mu * mu;
                const float rstd = rsqrtf(var + 1e-5f);
                a0 += (v[u].x - mu) * rstd;
                a1 += (v[u].y - mu) * rstd;
                a2 += (v[u].z - mu) * rstd;
                a3 += (v[u].w - mu) * rstd;
            }
        }

        __shared__ float part[8][D_DIM];
        part[warp][lane * 4 + 0] = a0;
        part[warp][lane * 4 + 1] = a1;
        part[warp][lane * 4 + 2] = a2;
        part[warp][lane * 4 + 3] = a3;
        __syncthreads();

        if (tid < D_DIM) {
            float sum = 0.f;
            #pragma unroll
            for (int w = 0; w < 8; w++) sum += part[w][tid];
            g_part[((size_t)z * I_DIM + i) * D_DIM + tid] = sum;
            __threadfence();
        }
        __syncthreads();
    }

    // ======= Phase B: last-arriver per row does the proj chain =======
    __shared__ int s_win;
    if (tid == 0) {
        const int old = atomicAdd(&g_cntA[i], 1);
        s_win = (old == 1);
        if (s_win) {
            g_cntA[i] = 0;      // reset for next replay
            __threadfence();    // acquire partner's partial
        }
    }
    __syncthreads();

    if (s_win) {
        const int h    = tid & 127;
        const int side = tid >> 7;
        __shared__ float xs[D_DIM];
        __shared__ float ls[H_DIM], rs[H_DIM];

        if (tid < D_DIM) {
            const float sum = g_part[i * D_DIM + tid]
                            + g_part[(size_t)(I_DIM + i) * D_DIM + tid];
            xs[tid] = sum * (1.f / (float)M_DIM) * ln_g[tid] + ln_b[tid];
        }
        __syncthreads();

        {   // stage 1: lm / rm
            const float* __restrict__ w1 = side ? wr : wl;
            float acc = side ? br[h] : bl[h];
            #pragma unroll 8
            for (int c = 0; c < D_DIM; c++)
                acc += xs[c] * w1[c * H_DIM + h];
            if (side) rs[h] = acc; else ls[h] = acc;
        }
        __syncthreads();
        {   // stage 2: L / R
            const float* __restrict__ v = side ? rs : ls;
            float acc = side ? bo[h] : 0.f;
            #pragma unroll 8
            for (int c = 0; c < H_DIM; c++)
                acc += v[c] * wo[c * D_DIM + h];
            if (side) g_R[i * D_DIM + h] = acc;
            else      g_L[i * D_DIM + h] = acc;
        }
        __threadfence();
        __syncthreads();
        if (tid == 0) atomicAdd(&g_readyRows, 1);
    }

    // ============ Phase C: all blocks broadcast-write ============
    if (tid == 0) {
        while (*(volatile int*)&g_readyRows < I_DIM) __nanosleep(128);
    }
    __syncthreads();

    {
        const int d4 = tid & 31;
        const int jl = tid >> 5;
        const float4* __restrict__ L4 = reinterpret_cast<const float4*>(g_L);
        const float4* __restrict__ R4 = reinterpret_cast<const float4*>(g_R);
        float4* __restrict__ o4 = reinterpret_cast<float4*>(out);

        // 8192 units of (i, 32 j's); 8 contiguous units per block
        #pragma unroll 1
        for (int k = 0; k < 8; k++) {
            const int u  = blockIdx.x * 8 + k;
            const int ui = u >> 4;
            const int j0 = (u & 15) * 32;
            const float4 Lv = __ldg(&L4[ui * 32 + d4]);
            #pragma unroll
            for (int p = 0; p < 4; p++) {
                const int j = j0 + jl + p * 8;
                const float4 Rv = __ldg(&R4[j * 32 + d4]);
                float4 o;
                o.x = Lv.x + Rv.x; o.y = Lv.y + Rv.y;
                o.z = Lv.z + Rv.z; o.w = Lv.w + Rv.w;
                __stcs(&o4[((size_t)ui * I_DIM + j) * 32 + d4], o);
            }
        }
    }

    // ============ epilogue: last block resets global counters ============
    __syncthreads();
    if (tid == 0) {
        const int old = atomicAdd(&g_done, 1);
        if (old == NBLK - 1) {
            g_readyRows = 0;
            g_done = 0;
            __threadfence();
        }
    }
}

// ---------------------------------------------------------------------------
extern "C" void kernel_launch(void* const* d_in, const int* in_sizes, int n_in,
                              void* d_out, int out_size)
{
    const float* x    = (const float*)d_in[0];
    const float* ln_g = (const float*)d_in[1];
    const float* ln_b = (const float*)d_in[2];
    const float* wl   = (const float*)d_in[3];
    const float* bl   = (const float*)d_in[4];
    const float* wr   = (const float*)d_in[5];
    const float* br   = (const float*)d_in[6];
    const float* wo   = (const float*)d_in[7];
    const float* bo   = (const float*)d_in[8];
    float* out = (float*)d_out;

    fused_kernel<<<NBLK, 256>>>(x, ln_g, ln_b, wl, bl, wr, br, wo, bo, out);
}